// round 2
// baseline (speedup 1.0000x reference)
#include <cuda_runtime.h>
#include <math_constants.h>
#include <cstdint>

// Problem shapes (fixed for this problem instance)
#define Bq 8
#define Cq 512
#define Tq 4096
#define Gq 2
#define NCq 1024
#define Eq 256
#define Nq 32768            // B*T
#define QELEMS 16777216     // B*C*T
#define IDXELEMS 131072     // 2*G*N

// Scratch (static __device__ globals; no allocation allowed)
__device__ float  g_xg[(size_t)Gq * Nq * Eq];   // packed x, later overwritten with residual
__device__ float  g_q1[(size_t)Gq * Nq * Eq];   // straight-through q1
__device__ float  g_sx2[Gq * Nq];               // per-vector sum of squares
__device__ float  g_cbsq[Gq * NCq];             // per-code sum of squares (recomputed per stage)
__device__ int    g_idx[2][Gq * Nq];            // argmin indices per stage
__device__ double g_loss[2];                    // sum of squared diffs per stage

// ---------------------------------------------------------------------------
// Zero the loss accumulators (must run every replay: graph-captured)
// ---------------------------------------------------------------------------
__global__ void zero_kernel() {
    if (threadIdx.x < 2) g_loss[threadIdx.x] = 0.0;
}

// ---------------------------------------------------------------------------
// Pack: xin[b][c][t] -> g_xg[g][n=b*T+t][e], tiled 32x32 transpose
// grid: (T/32 * E/32, G, B), block: (32, 8)
// ---------------------------------------------------------------------------
__global__ void pack_kernel(const float* __restrict__ xin) {
    __shared__ float tile[32][33];
    int bT = blockIdx.x >> 3, bE = blockIdx.x & 7;
    int g = blockIdx.y, b = blockIdx.z;
    int t0 = bT * 32, e0 = bE * 32;
    int tx = threadIdx.x, ty = threadIdx.y;
#pragma unroll
    for (int r = 0; r < 4; ++r) {
        int ei = ty * 4 + r;
        tile[ei][tx] = xin[((size_t)b * Cq + g * Eq + e0 + ei) * Tq + t0 + tx];
    }
    __syncthreads();
#pragma unroll
    for (int r = 0; r < 4; ++r) {
        int tl = ty * 4 + r;
        g_xg[((size_t)g * Nq + (size_t)b * Tq + t0 + tl) * Eq + e0 + tx] = tile[tx][tl];
    }
}

// ---------------------------------------------------------------------------
// Row sum-of-squares (one warp per 256-float row)
// block = 256 threads (8 warps); grid = rows/8
// ---------------------------------------------------------------------------
__global__ void rowsumsq_x_kernel() {   // g_xg rows -> g_sx2
    int w = blockIdx.x * 8 + (threadIdx.x >> 5);
    int lane = threadIdx.x & 31;
    const float4* rp = (const float4*)(g_xg + (size_t)w * Eq);
    float s = 0.f;
#pragma unroll
    for (int r = 0; r < 2; ++r) {
        float4 v = rp[lane + 32 * r];
        s = fmaf(v.x, v.x, s); s = fmaf(v.y, v.y, s);
        s = fmaf(v.z, v.z, s); s = fmaf(v.w, v.w, s);
    }
#pragma unroll
    for (int o = 16; o; o >>= 1) s += __shfl_xor_sync(0xffffffffu, s, o);
    if (lane == 0) g_sx2[w] = s;
}

__global__ void rowsumsq_cb_kernel(const float* __restrict__ cb) {  // codebook rows -> g_cbsq
    int w = blockIdx.x * 8 + (threadIdx.x >> 5);
    int lane = threadIdx.x & 31;
    const float4* rp = (const float4*)(cb + (size_t)w * Eq);
    float s = 0.f;
#pragma unroll
    for (int r = 0; r < 2; ++r) {
        float4 v = rp[lane + 32 * r];
        s = fmaf(v.x, v.x, s); s = fmaf(v.y, v.y, s);
        s = fmaf(v.z, v.z, s); s = fmaf(v.w, v.w, s);
    }
#pragma unroll
    for (int o = 16; o; o >>= 1) s += __shfl_xor_sync(0xffffffffu, s, o);
    if (lane == 0) g_cbsq[w] = s;
}

// ---------------------------------------------------------------------------
// Distance GEMM + fused argmin.
// 128n x 128c tile, K=256 fully resident in smem (n-major -> plain copy),
// codebook streamed in 32-k chunks (k4-major float4 layout, conflict-free).
// Strided micro-tile ownership: thread (tx,ty) owns n = ty+16i, c = tx+16j.
// d = fl(fl(sumx2 + sumcb2) - fl(2*dot))  (mirrors reference op structure)
// grid: (N/128, G), block 256, dynamic smem 147456 B
// ---------------------------------------------------------------------------
__global__ void __launch_bounds__(256, 1) argmin_kernel(
    const float* __restrict__ cb, int stage)
{
    extern __shared__ float smem[];
    float4* xs4  = (float4*)smem;                 // [128 n][64 k4]
    float4* cbs4 = (float4*)(smem + 128 * Eq);    // [8 k4][128 c]
    const int tid = threadIdx.x;
    const int g  = blockIdx.y;
    const int n0 = blockIdx.x * 128;

    const float4* xrow = (const float4*)(g_xg + ((size_t)g * Nq + n0) * Eq);
#pragma unroll
    for (int it = 0; it < 32; ++it)
        xs4[it * 256 + tid] = xrow[it * 256 + tid];

    const int tx = tid & 15;
    const int ty = tid >> 4;

    float bestv[8];
    int   besti[8];
#pragma unroll
    for (int i = 0; i < 8; ++i) { bestv[i] = CUDART_INF_F; besti[i] = 0; }

    const float* cbg = cb + (size_t)g * NCq * Eq;

    for (int ct = 0; ct < 8; ++ct) {
        const int c0 = ct * 128;
        float acc[8][8];
#pragma unroll
        for (int i = 0; i < 8; ++i)
#pragma unroll
            for (int j = 0; j < 8; ++j) acc[i][j] = 0.f;

        for (int ch = 0; ch < 8; ++ch) {
            __syncthreads();
#pragma unroll
            for (int it = 0; it < 4; ++it) {
                int idx = it * 256 + tid;
                int c = idx >> 3, k4 = idx & 7;
                cbs4[k4 * 128 + c] =
                    ((const float4*)(cbg + (size_t)(c0 + c) * Eq))[ch * 8 + k4];
            }
            __syncthreads();
#pragma unroll
            for (int k4 = 0; k4 < 8; ++k4) {
                float4 a[8];
#pragma unroll
                for (int i = 0; i < 8; ++i)
                    a[i] = xs4[(ty + 16 * i) * 64 + ch * 8 + k4];
#pragma unroll
                for (int j = 0; j < 8; ++j) {
                    float4 b = cbs4[k4 * 128 + tx + 16 * j];
#pragma unroll
                    for (int i = 0; i < 8; ++i) {
                        acc[i][j] = fmaf(a[i].x, b.x, acc[i][j]);
                        acc[i][j] = fmaf(a[i].y, b.y, acc[i][j]);
                        acc[i][j] = fmaf(a[i].z, b.z, acc[i][j]);
                        acc[i][j] = fmaf(a[i].w, b.w, acc[i][j]);
                    }
                }
            }
        }
        // epilogue: distances + running argmin for this c-tile
#pragma unroll
        for (int i = 0; i < 8; ++i) {
            float sx = g_sx2[g * Nq + n0 + ty + 16 * i];
#pragma unroll
            for (int j = 0; j < 8; ++j) {
                int c = c0 + tx + 16 * j;
                float t = sx + g_cbsq[g * NCq + c];
                float d = t - 2.0f * acc[i][j];
                if (d < bestv[i] || (d == bestv[i] && c < besti[i])) {
                    bestv[i] = d; besti[i] = c;
                }
            }
        }
    }

    // cross-tx reduction (lowest index wins on exact ties, like jnp.argmin)
    __syncthreads();
    float* redv = smem + 128 * Eq;           // reuse cbs region: 2048 floats
    int*   redi = (int*)(redv + 2048);       // + 2048 ints
#pragma unroll
    for (int i = 0; i < 8; ++i) {
        int nl = ty + 16 * i;
        redv[nl * 16 + tx] = bestv[i];
        redi[nl * 16 + tx] = besti[i];
    }
    __syncthreads();
    if (tid < 128) {
        float bv = redv[tid * 16];
        int   bi = redi[tid * 16];
#pragma unroll
        for (int t = 1; t < 16; ++t) {
            float v = redv[tid * 16 + t];
            int  ii = redi[tid * 16 + t];
            if (v < bv || (v == bv && ii < bi)) { bv = v; bi = ii; }
        }
        g_idx[stage][g * Nq + n0 + tid] = bi;
    }
}

// ---------------------------------------------------------------------------
// Stage-1 epilogue: gather z_q1, straight-through q1, residual (in-place into
// g_xg), loss1 accumulation. One warp per (g,n) row.
// block 256 (8 warps), grid G*N/8
// ---------------------------------------------------------------------------
__global__ void residual_kernel(const float* __restrict__ cb) {
    int w = blockIdx.x * 8 + (threadIdx.x >> 5);
    int lane = threadIdx.x & 31;
    int g = w >> 15;
    int n = w & (Nq - 1);
    size_t base = ((size_t)g * Nq + n) * Eq;
    int id = g_idx[0][g * Nq + n];
    const float4* qrow = (const float4*)(cb + ((size_t)g * NCq + id) * Eq);
    float4* xr  = (float4*)(g_xg + base);
    float4* q1r = (float4*)(g_q1 + base);
    double ls = 0.0;
#pragma unroll
    for (int r = 0; r < 2; ++r) {
        float4 x = xr[lane + 32 * r];
        float4 q = qrow[lane + 32 * r];
        float4 qs, rr;
        float d;
        d = q.x - x.x; ls += (double)d * d; qs.x = x.x + d; rr.x = x.x - qs.x;
        d = q.y - x.y; ls += (double)d * d; qs.y = x.y + d; rr.y = x.y - qs.y;
        d = q.z - x.z; ls += (double)d * d; qs.z = x.z + d; rr.z = x.z - qs.z;
        d = q.w - x.w; ls += (double)d * d; qs.w = x.w + d; rr.w = x.w - qs.w;
        q1r[lane + 32 * r] = qs;
        xr[lane + 32 * r]  = rr;
    }
#pragma unroll
    for (int o = 16; o; o >>= 1) ls += __shfl_xor_sync(0xffffffffu, ls, o);
    if (lane == 0) atomicAdd(&g_loss[0], ls);
}

// ---------------------------------------------------------------------------
// Final: gather z_q2, straight-through q2, out = q1_st + q2_st transposed back
// to [B,C,T]; loss2 accumulation. Tiled 32x32 transpose.
// grid: (T/32 * E/32, G, B), block (32, 8)
// ---------------------------------------------------------------------------
__global__ void final_kernel(const float* __restrict__ cb2, float* __restrict__ out) {
    __shared__ float tile[32][33];
    __shared__ int sidx[32];
    __shared__ double wsum[8];
    int bT = blockIdx.x >> 3, bE = blockIdx.x & 7;
    int g = blockIdx.y, b = blockIdx.z;
    int t0 = bT * 32, e0 = bE * 32;
    int tx = threadIdx.x, ty = threadIdx.y;
    int tid = ty * 32 + tx;
    if (ty == 0) sidx[tx] = g_idx[1][g * Nq + b * Tq + t0 + tx];
    __syncthreads();
    double ls = 0.0;
#pragma unroll
    for (int r = 0; r < 4; ++r) {
        int tl = ty * 4 + r;
        size_t n = (size_t)b * Tq + t0 + tl;
        size_t base = ((size_t)g * Nq + n) * Eq + e0 + tx;
        float rr = g_xg[base];                                    // residual
        float zq = cb2[((size_t)g * NCq + sidx[tl]) * Eq + e0 + tx];
        float d = zq - rr;
        ls += (double)d * d;
        float q2st = rr + d;                                      // fl(r + fl(zq-r))
        tile[tl][tx] = g_q1[base] + q2st;
    }
    __syncthreads();
#pragma unroll
    for (int r = 0; r < 4; ++r) {
        int ei = ty * 4 + r;
        out[((size_t)b * Cq + g * Eq + e0 + ei) * Tq + t0 + tx] = tile[tx][ei];
    }
#pragma unroll
    for (int o = 16; o; o >>= 1) ls += __shfl_xor_sync(0xffffffffu, ls, o);
    if ((tid & 31) == 0) wsum[tid >> 5] = ls;
    __syncthreads();
    if (tid == 0) {
        double t = 0.0;
#pragma unroll
        for (int i = 0; i < 8; ++i) t += wsum[i];
        atomicAdd(&g_loss[1], t);
    }
}

// ---------------------------------------------------------------------------
// Tail: loss scalar + indices (cast to float) into d_out
// ---------------------------------------------------------------------------
__global__ void tail_kernel(float* __restrict__ out) {
    int t = blockIdx.x * blockDim.x + threadIdx.x;
    if (t == 0) {
        double l = 0.625 * (g_loss[0] + g_loss[1]) / (double)QELEMS;
        out[QELEMS] = (float)l;
    }
    if (t < IDXELEMS) out[QELEMS + 1 + t] = (float)(&g_idx[0][0])[t];
}

// ---------------------------------------------------------------------------
extern "C" void kernel_launch(void* const* d_in, const int* in_sizes, int n_in,
                              void* d_out, int out_size) {
    const float* xin = (const float*)d_in[0];
    const float* cb1 = (const float*)d_in[1];
    const float* cb2 = (const float*)d_in[2];
    float* out = (float*)d_out;

    const int ARGMIN_SMEM = 128 * Eq * 4 + 16384;   // 147456 B
    cudaFuncSetAttribute(argmin_kernel,
                         cudaFuncAttributeMaxDynamicSharedMemorySize, ARGMIN_SMEM);

    zero_kernel<<<1, 32>>>();
    pack_kernel<<<dim3((Tq / 32) * (Eq / 32), Gq, Bq), dim3(32, 8)>>>(xin);

    // Stage 1
    rowsumsq_x_kernel<<<(Gq * Nq) / 8, 256>>>();
    rowsumsq_cb_kernel<<<(Gq * NCq) / 8, 256>>>(cb1);
    argmin_kernel<<<dim3(Nq / 128, Gq), 256, ARGMIN_SMEM>>>(cb1, 0);
    residual_kernel<<<(Gq * Nq) / 8, 256>>>(cb1);

    // Stage 2 (g_xg now holds the residual)
    rowsumsq_x_kernel<<<(Gq * Nq) / 8, 256>>>();
    rowsumsq_cb_kernel<<<(Gq * NCq) / 8, 256>>>(cb2);
    argmin_kernel<<<dim3(Nq / 128, Gq), 256, ARGMIN_SMEM>>>(cb2, 1);

    final_kernel<<<dim3((Tq / 32) * (Eq / 32), Gq, Bq), dim3(32, 8)>>>(cb2, out);

    if (out_size >= QELEMS + 1 + IDXELEMS)
        tail_kernel<<<(IDXELEMS + 255) / 256, 256>>>(out);
}

// round 5
// speedup vs baseline: 1.1323x; 1.1323x over previous
#include <cuda_runtime.h>
#include <math_constants.h>
#include <cstdint>

// Problem shapes (fixed)
#define Bq 8
#define Cq 512
#define Tq 4096
#define Gq 2
#define NCq 1024
#define Eq 256
#define Nq 32768            // B*T
#define QELEMS 16777216     // B*C*T
#define IDXELEMS 131072     // 2*G*N

// Scratch
__device__ float  g_xg[(size_t)Gq * Nq * Eq];   // packed x, later residual
__device__ float  g_q1[(size_t)Gq * Nq * Eq];   // straight-through q1
__device__ float  g_sx2[Gq * Nq];
__device__ float  g_cbsq[Gq * NCq];
__device__ int    g_idx[2][Gq * Nq];
__device__ double g_loss[2];

// ---------------------------------------------------------------------------
__global__ void zero_kernel() {
    if (threadIdx.x < 2) g_loss[threadIdx.x] = 0.0;
}

// ---------------------------------------------------------------------------
// Pack: xin[b][c][t] -> g_xg[g][n=b*T+t][e]
// ---------------------------------------------------------------------------
__global__ void pack_kernel(const float* __restrict__ xin) {
    __shared__ float tile[32][33];
    int bT = blockIdx.x >> 3, bE = blockIdx.x & 7;
    int g = blockIdx.y, b = blockIdx.z;
    int t0 = bT * 32, e0 = bE * 32;
    int tx = threadIdx.x, ty = threadIdx.y;
#pragma unroll
    for (int r = 0; r < 4; ++r) {
        int ei = ty * 4 + r;
        tile[ei][tx] = xin[((size_t)b * Cq + g * Eq + e0 + ei) * Tq + t0 + tx];
    }
    __syncthreads();
#pragma unroll
    for (int r = 0; r < 4; ++r) {
        int tl = ty * 4 + r;
        g_xg[((size_t)g * Nq + (size_t)b * Tq + t0 + tl) * Eq + e0 + tx] = tile[tx][tl];
    }
}

// ---------------------------------------------------------------------------
// Row sum-of-squares
// ---------------------------------------------------------------------------
__global__ void rowsumsq_x_kernel() {
    int w = blockIdx.x * 8 + (threadIdx.x >> 5);
    int lane = threadIdx.x & 31;
    const float4* rp = (const float4*)(g_xg + (size_t)w * Eq);
    float s = 0.f;
#pragma unroll
    for (int r = 0; r < 2; ++r) {
        float4 v = rp[lane + 32 * r];
        s = fmaf(v.x, v.x, s); s = fmaf(v.y, v.y, s);
        s = fmaf(v.z, v.z, s); s = fmaf(v.w, v.w, s);
    }
#pragma unroll
    for (int o = 16; o; o >>= 1) s += __shfl_xor_sync(0xffffffffu, s, o);
    if (lane == 0) g_sx2[w] = s;
}

__global__ void rowsumsq_cb_kernel(const float* __restrict__ cb) {
    int w = blockIdx.x * 8 + (threadIdx.x >> 5);
    int lane = threadIdx.x & 31;
    const float4* rp = (const float4*)(cb + (size_t)w * Eq);
    float s = 0.f;
#pragma unroll
    for (int r = 0; r < 2; ++r) {
        float4 v = rp[lane + 32 * r];
        s = fmaf(v.x, v.x, s); s = fmaf(v.y, v.y, s);
        s = fmaf(v.z, v.z, s); s = fmaf(v.w, v.w, s);
    }
#pragma unroll
    for (int o = 16; o; o >>= 1) s += __shfl_xor_sync(0xffffffffu, s, o);
    if (lane == 0) g_cbsq[w] = s;
}

// ---------------------------------------------------------------------------
// Packed-fp32 helpers
// ---------------------------------------------------------------------------
__device__ __forceinline__ unsigned long long fma2(
    unsigned long long a, unsigned long long b, unsigned long long c) {
    unsigned long long d;
    asm("fma.rn.f32x2 %0, %1, %2, %3;" : "=l"(d) : "l"(a), "l"(b), "l"(c));
    return d;
}
__device__ __forceinline__ unsigned long long dup2(float s) {
    unsigned u = __float_as_uint(s);
    unsigned long long r;
    asm("mov.b64 %0, {%1, %2};" : "=l"(r) : "r"(u), "r"(u));
    return r;
}
__device__ __forceinline__ float lo32(unsigned long long v) {
    return __uint_as_float((unsigned)(v & 0xffffffffull));
}
__device__ __forceinline__ float hi32(unsigned long long v) {
    return __uint_as_float((unsigned)(v >> 32));
}
__device__ __forceinline__ unsigned smem_u32(const void* p) {
    return (unsigned)__cvta_generic_to_shared(p);
}
__device__ __forceinline__ void cpasync16(unsigned dst, const void* src) {
    asm volatile("cp.async.cg.shared.global [%0], [%1], 16;" :: "r"(dst), "l"(src));
}

// ---------------------------------------------------------------------------
// Distance GEMM + fused argmin, packed fp32 (f32x2), cp.async double buffer.
// Tile 128n x 128c, K=256 resident for x (k-major smem layout), codebook
// streamed in 32-k chunks. Thread (tx,ty) owns n = 8*ty + {0..7} (4 f32x2
// pairs) and c = tx + 16*j, j=0..7. Per-lane accumulation order identical to
// the scalar kernel (bitwise-identical distances).
// smem: xs[256k][128n] (128KB) | cbs[2][8k4][128c] float4 (32KB) -> 160KB
// grid: (N/128, G), block 256
// ---------------------------------------------------------------------------
#define ARGMIN_SMEM_BYTES (131072 + 32768)

__global__ void __launch_bounds__(256, 1) argmin_kernel(
    const float* __restrict__ cb, int stage)
{
    extern __shared__ float smem[];
    float*  xs   = smem;                          // [256][128]
    float4* cbs4 = (float4*)(smem + 32768);       // [2][1024]
    const int tid = threadIdx.x;
    const int tx = tid & 15;
    const int ty = tid >> 4;
    const int g  = blockIdx.y;
    const int n0 = blockIdx.x * 128;
    const float* cbg = cb + (size_t)g * NCq * Eq;

    // Prefetch codebook chunks 0 and 1
#pragma unroll
    for (int q = 0; q < 2; ++q) {
        int ct = q >> 3, ch = q & 7;
#pragma unroll
        for (int it = 0; it < 4; ++it) {
            int idx = it * 256 + tid;
            int k4 = idx >> 7, c = idx & 127;
            const float* src = cbg + (size_t)(ct * 128 + c) * Eq + ch * 32 + k4 * 4;
            cpasync16(smem_u32(&cbs4[(q & 1) * 1024 + k4 * 128 + c]), src);
        }
        asm volatile("cp.async.commit_group;");
    }

    // Fill xs (k-major transpose of the 128-row x tile)
#pragma unroll
    for (int it = 0; it < 32; ++it) {
        int n  = (tid & 31) + 32 * (it & 3);
        int k4 = (tid >> 5) + 8 * (it >> 2);
        float4 v = *(const float4*)(g_xg + ((size_t)g * Nq + n0 + n) * Eq + k4 * 4);
        xs[(k4 * 4 + 0) * 128 + n] = v.x;
        xs[(k4 * 4 + 1) * 128 + n] = v.y;
        xs[(k4 * 4 + 2) * 128 + n] = v.z;
        xs[(k4 * 4 + 3) * 128 + n] = v.w;
    }

    // Per-thread row sums (8 rows)
    float sx[8];
#pragma unroll
    for (int r = 0; r < 8; ++r) sx[r] = g_sx2[g * Nq + n0 + 8 * ty + r];

    unsigned long long acc[4][8];
    float bestv[8];
    int   besti[8];
#pragma unroll
    for (int r = 0; r < 8; ++r) { bestv[r] = CUDART_INF_F; besti[r] = 0; }

    for (int q = 0; q < 64; ++q) {
        const int ct = q >> 3, ch = q & 7;
        asm volatile("cp.async.wait_group 1;");
        __syncthreads();

        if (ch == 0) {
#pragma unroll
            for (int ip = 0; ip < 4; ++ip)
#pragma unroll
                for (int j = 0; j < 8; ++j) acc[ip][j] = 0ull;
        }

        const float4* cbuf = cbs4 + (q & 1) * 1024;
#pragma unroll
        for (int k4 = 0; k4 < 8; ++k4) {
            float4 bv[8];
#pragma unroll
            for (int j = 0; j < 8; ++j) bv[j] = cbuf[k4 * 128 + tx + 16 * j];
            const int kb = ch * 32 + k4 * 4;
#pragma unroll
            for (int ke = 0; ke < 4; ++ke) {
                const ulonglong2* ap =
                    (const ulonglong2*)(xs + (kb + ke) * 128 + 8 * ty);
                ulonglong2 A0 = ap[0];   // pairs (n0,n1),(n2,n3)
                ulonglong2 A1 = ap[1];   // pairs (n4,n5),(n6,n7)
#pragma unroll
                for (int j = 0; j < 8; ++j) {
                    float s = (ke == 0) ? bv[j].x : (ke == 1) ? bv[j].y
                            : (ke == 2) ? bv[j].z : bv[j].w;
                    unsigned long long bd = dup2(s);
                    acc[0][j] = fma2(A0.x, bd, acc[0][j]);
                    acc[1][j] = fma2(A0.y, bd, acc[1][j]);
                    acc[2][j] = fma2(A1.x, bd, acc[2][j]);
                    acc[3][j] = fma2(A1.y, bd, acc[3][j]);
                }
            }
        }

        if (ch == 7) {
            // distances + running argmin (c strictly ascending within thread)
#pragma unroll
            for (int j = 0; j < 8; ++j) {
                int c = ct * 128 + tx + 16 * j;
                float cq = g_cbsq[g * NCq + c];
#pragma unroll
                for (int ip = 0; ip < 4; ++ip) {
                    float d0 = (sx[2 * ip]     + cq) - 2.0f * lo32(acc[ip][j]);
                    float d1 = (sx[2 * ip + 1] + cq) - 2.0f * hi32(acc[ip][j]);
                    if (d0 < bestv[2 * ip])     { bestv[2 * ip]     = d0; besti[2 * ip]     = c; }
                    if (d1 < bestv[2 * ip + 1]) { bestv[2 * ip + 1] = d1; besti[2 * ip + 1] = c; }
                }
            }
        }

        __syncthreads();
        // Prefetch chunk q+2 into buffer (q&1); always commit (keeps group
        // accounting uniform so wait_group 1 is exact for every q).
        int qn = q + 2;
        if (qn < 64) {
            int ctn = qn >> 3, chn = qn & 7;
#pragma unroll
            for (int it = 0; it < 4; ++it) {
                int idx = it * 256 + tid;
                int k4 = idx >> 7, c = idx & 127;
                const float* src = cbg + (size_t)(ctn * 128 + c) * Eq + chn * 32 + k4 * 4;
                cpasync16(smem_u32(&cbs4[(q & 1) * 1024 + k4 * 128 + c]), src);
            }
        }
        asm volatile("cp.async.commit_group;");
    }

    // Cross-tx argmin reduction (lowest index wins on exact ties)
    __syncthreads();
    float* redv = smem + 32768;            // reuse cbs region
    int*   redi = (int*)(redv + 2048);
#pragma unroll
    for (int r = 0; r < 8; ++r) {
        int nl = 8 * ty + r;
        redv[nl * 16 + tx] = bestv[r];
        redi[nl * 16 + tx] = besti[r];
    }
    __syncthreads();
    if (tid < 128) {
        float bv = redv[tid * 16];
        int   bi = redi[tid * 16];
#pragma unroll
        for (int t = 1; t < 16; ++t) {
            float v = redv[tid * 16 + t];
            int  ii = redi[tid * 16 + t];
            if (v < bv || (v == bv && ii < bi)) { bv = v; bi = ii; }
        }
        g_idx[stage][g * Nq + n0 + tid] = bi;
    }
}

// ---------------------------------------------------------------------------
// Stage-1 epilogue: gather z_q1, straight-through, residual, loss1
// ---------------------------------------------------------------------------
__global__ void residual_kernel(const float* __restrict__ cb) {
    int w = blockIdx.x * 8 + (threadIdx.x >> 5);
    int lane = threadIdx.x & 31;
    int g = w >> 15;
    int n = w & (Nq - 1);
    size_t base = ((size_t)g * Nq + n) * Eq;
    int id = g_idx[0][g * Nq + n];
    const float4* qrow = (const float4*)(cb + ((size_t)g * NCq + id) * Eq);
    float4* xr  = (float4*)(g_xg + base);
    float4* q1r = (float4*)(g_q1 + base);
    double ls = 0.0;
#pragma unroll
    for (int r = 0; r < 2; ++r) {
        float4 x = xr[lane + 32 * r];
        float4 q = qrow[lane + 32 * r];
        float4 qs, rr;
        float d;
        d = q.x - x.x; ls += (double)d * d; qs.x = x.x + d; rr.x = x.x - qs.x;
        d = q.y - x.y; ls += (double)d * d; qs.y = x.y + d; rr.y = x.y - qs.y;
        d = q.z - x.z; ls += (double)d * d; qs.z = x.z + d; rr.z = x.z - qs.z;
        d = q.w - x.w; ls += (double)d * d; qs.w = x.w + d; rr.w = x.w - qs.w;
        q1r[lane + 32 * r] = qs;
        xr[lane + 32 * r]  = rr;
    }
#pragma unroll
    for (int o = 16; o; o >>= 1) ls += __shfl_xor_sync(0xffffffffu, ls, o);
    if (lane == 0) atomicAdd(&g_loss[0], ls);
}

// ---------------------------------------------------------------------------
// Final: out = q1_st + q2_st transposed to [B,C,T]; loss2
// ---------------------------------------------------------------------------
__global__ void final_kernel(const float* __restrict__ cb2, float* __restrict__ out) {
    __shared__ float tile[32][33];
    __shared__ int sidx[32];
    __shared__ double wsum[8];
    int bT = blockIdx.x >> 3, bE = blockIdx.x & 7;
    int g = blockIdx.y, b = blockIdx.z;
    int t0 = bT * 32, e0 = bE * 32;
    int tx = threadIdx.x, ty = threadIdx.y;
    int tid = ty * 32 + tx;
    if (ty == 0) sidx[tx] = g_idx[1][g * Nq + b * Tq + t0 + tx];
    __syncthreads();
    double ls = 0.0;
#pragma unroll
    for (int r = 0; r < 4; ++r) {
        int tl = ty * 4 + r;
        size_t n = (size_t)b * Tq + t0 + tl;
        size_t base = ((size_t)g * Nq + n) * Eq + e0 + tx;
        float rr = g_xg[base];
        float zq = cb2[((size_t)g * NCq + sidx[tl]) * Eq + e0 + tx];
        float d = zq - rr;
        ls += (double)d * d;
        float q2st = rr + d;
        tile[tl][tx] = g_q1[base] + q2st;
    }
    __syncthreads();
#pragma unroll
    for (int r = 0; r < 4; ++r) {
        int ei = ty * 4 + r;
        out[((size_t)b * Cq + g * Eq + e0 + ei) * Tq + t0 + tx] = tile[tx][ei];
    }
#pragma unroll
    for (int o = 16; o; o >>= 1) ls += __shfl_xor_sync(0xffffffffu, ls, o);
    if ((tid & 31) == 0) wsum[tid >> 5] = ls;
    __syncthreads();
    if (tid == 0) {
        double t = 0.0;
#pragma unroll
        for (int i = 0; i < 8; ++i) t += wsum[i];
        atomicAdd(&g_loss[1], t);
    }
}

// ---------------------------------------------------------------------------
__global__ void tail_kernel(float* __restrict__ out) {
    int t = blockIdx.x * blockDim.x + threadIdx.x;
    if (t == 0) {
        double l = 0.625 * (g_loss[0] + g_loss[1]) / (double)QELEMS;
        out[QELEMS] = (float)l;
    }
    if (t < IDXELEMS) out[QELEMS + 1 + t] = (float)(&g_idx[0][0])[t];
}

// ---------------------------------------------------------------------------
extern "C" void kernel_launch(void* const* d_in, const int* in_sizes, int n_in,
                              void* d_out, int out_size) {
    const float* xin = (const float*)d_in[0];
    const float* cb1 = (const float*)d_in[1];
    const float* cb2 = (const float*)d_in[2];
    float* out = (float*)d_out;

    cudaFuncSetAttribute(argmin_kernel,
                         cudaFuncAttributeMaxDynamicSharedMemorySize,
                         ARGMIN_SMEM_BYTES);

    zero_kernel<<<1, 32>>>();
    pack_kernel<<<dim3((Tq / 32) * (Eq / 32), Gq, Bq), dim3(32, 8)>>>(xin);

    // Stage 1
    rowsumsq_x_kernel<<<(Gq * Nq) / 8, 256>>>();
    rowsumsq_cb_kernel<<<(Gq * NCq) / 8, 256>>>(cb1);
    argmin_kernel<<<dim3(Nq / 128, Gq), 256, ARGMIN_SMEM_BYTES>>>(cb1, 0);
    residual_kernel<<<(Gq * Nq) / 8, 256>>>(cb1);

    // Stage 2 (g_xg now holds the residual)
    rowsumsq_x_kernel<<<(Gq * Nq) / 8, 256>>>();
    rowsumsq_cb_kernel<<<(Gq * NCq) / 8, 256>>>(cb2);
    argmin_kernel<<<dim3(Nq / 128, Gq), 256, ARGMIN_SMEM_BYTES>>>(cb2, 1);

    final_kernel<<<dim3((Tq / 32) * (Eq / 32), Gq, Bq), dim3(32, 8)>>>(cb2, out);

    if (out_size >= QELEMS + 1 + IDXELEMS)
        tail_kernel<<<(IDXELEMS + 255) / 256, 256>>>(out);
}